// round 6
// baseline (speedup 1.0000x reference)
#include <cuda_runtime.h>
#include <cuda_bf16.h>
#include <cstdint>

// EfficientReynoldsFeatureOperator:
//   x:  (B=8, N=8192, D=512) fp32
//   W:  (D=512, R=128)       fp32
//   pw: (R=128)              fp32
//   out:(B, N, R) fp32,  out[b,n,r] = (mean_n(x[b]) @ W)[r] * pw[r]
// Using mean_n(x @ W) == (mean_n x) @ W.

#define B_DIM 8
#define N_DIM 8192
#define D_DIM 512
#define R_DIM 128
#define CHUNKS 256
#define ROWS_PER_CHUNK (N_DIM / CHUNKS)     // 32
#define G2 32                                // k2a blocks per batch
#define CHUNKS_PER_G2 (CHUNKS / G2)          // 8

__device__ float g_partial[B_DIM * CHUNKS * D_DIM];   // 4 MB scratch (L2-hot)
__device__ float g_p2[B_DIM * G2 * D_DIM];            // 512 KB
__device__ float g_y[B_DIM * R_DIM];                  // 4 KB

// ---------------------------------------------------------------------------
// K1: partial column sums of x over n. (unchanged from round 4)
// ---------------------------------------------------------------------------
__global__ __launch_bounds__(128, 8) void k1_colsum_partial(const float* __restrict__ x) {
    const int chunk = blockIdx.x;
    const int b     = blockIdx.y;
    const int d4    = threadIdx.x;            // 0..127

    const float4* xrow = reinterpret_cast<const float4*>(
        x + (size_t)(b * N_DIM + chunk * ROWS_PER_CHUNK) * D_DIM);

    float4 a0 = make_float4(0.f, 0.f, 0.f, 0.f);
    float4 a1 = make_float4(0.f, 0.f, 0.f, 0.f);

#pragma unroll
    for (int i = 0; i < ROWS_PER_CHUNK; i += 8) {
        float4 v0 = __ldcs(&xrow[(size_t)(i + 0) * (D_DIM / 4) + d4]);
        float4 v1 = __ldcs(&xrow[(size_t)(i + 1) * (D_DIM / 4) + d4]);
        float4 v2 = __ldcs(&xrow[(size_t)(i + 2) * (D_DIM / 4) + d4]);
        float4 v3 = __ldcs(&xrow[(size_t)(i + 3) * (D_DIM / 4) + d4]);
        float4 v4 = __ldcs(&xrow[(size_t)(i + 4) * (D_DIM / 4) + d4]);
        float4 v5 = __ldcs(&xrow[(size_t)(i + 5) * (D_DIM / 4) + d4]);
        float4 v6 = __ldcs(&xrow[(size_t)(i + 6) * (D_DIM / 4) + d4]);
        float4 v7 = __ldcs(&xrow[(size_t)(i + 7) * (D_DIM / 4) + d4]);
        a0.x += v0.x; a0.y += v0.y; a0.z += v0.z; a0.w += v0.w;
        a1.x += v1.x; a1.y += v1.y; a1.z += v1.z; a1.w += v1.w;
        a0.x += v2.x; a0.y += v2.y; a0.z += v2.z; a0.w += v2.w;
        a1.x += v3.x; a1.y += v3.y; a1.z += v3.z; a1.w += v3.w;
        a0.x += v4.x; a0.y += v4.y; a0.z += v4.z; a0.w += v4.w;
        a1.x += v5.x; a1.y += v5.y; a1.z += v5.z; a1.w += v5.w;
        a0.x += v6.x; a0.y += v6.y; a0.z += v6.z; a0.w += v6.w;
        a1.x += v7.x; a1.y += v7.y; a1.z += v7.z; a1.w += v7.w;
    }
    a0.x += a1.x; a0.y += a1.y; a0.z += a1.z; a0.w += a1.w;

    float4* p = reinterpret_cast<float4*>(
        g_partial + (size_t)(b * CHUNKS + chunk) * D_DIM);
    p[d4] = a0;
}

// ---------------------------------------------------------------------------
// K2a: first-level partial reduction, 256 blocks. (unchanged)
// ---------------------------------------------------------------------------
__global__ __launch_bounds__(128) void k2a_reduce(void) {
    const int j  = blockIdx.x;
    const int b  = blockIdx.y;
    const int d4 = threadIdx.x;

    const float4* base = reinterpret_cast<const float4*>(
        g_partial + (size_t)(b * CHUNKS + j * CHUNKS_PER_G2) * D_DIM);

    float4 acc = make_float4(0.f, 0.f, 0.f, 0.f);
#pragma unroll
    for (int c = 0; c < CHUNKS_PER_G2; ++c) {
        float4 v = base[(size_t)c * (D_DIM / 4) + d4];
        acc.x += v.x; acc.y += v.y; acc.z += v.z; acc.w += v.w;
    }
    float4* p = reinterpret_cast<float4*>(
        g_p2 + (size_t)(b * G2 + j) * D_DIM);
    p[d4] = acc;
}

// ---------------------------------------------------------------------------
// K2b: per batch: finish reduction, project, scale. (unchanged)
// ---------------------------------------------------------------------------
__global__ __launch_bounds__(512) void k2b_finish_and_project(
    const float* __restrict__ W, const float* __restrict__ pw) {
    __shared__ float s_part[4][D_DIM];
    __shared__ float s_mean[D_DIM];
    __shared__ float s_red[16][R_DIM];
    const int b = blockIdx.x;
    const int t = threadIdx.x;
    const int g  = t >> 7;        // 0..3
    const int d4 = t & 127;       // 0..127

    const float4* pbase = reinterpret_cast<const float4*>(
        g_p2 + (size_t)b * G2 * D_DIM);

    float4 acc = make_float4(0.f, 0.f, 0.f, 0.f);
#pragma unroll
    for (int c = g; c < G2; c += 4) {
        float4 v = pbase[(size_t)c * (D_DIM / 4) + d4];
        acc.x += v.x; acc.y += v.y; acc.z += v.z; acc.w += v.w;
    }
    s_part[g][4 * d4 + 0] = acc.x;
    s_part[g][4 * d4 + 1] = acc.y;
    s_part[g][4 * d4 + 2] = acc.z;
    s_part[g][4 * d4 + 3] = acc.w;
    __syncthreads();

    s_mean[t] = (s_part[0][t] + s_part[1][t] + s_part[2][t] + s_part[3][t])
                * (1.0f / (float)N_DIM);
    __syncthreads();

    const int w    = t >> 5;
    const int lane = t & 31;
    float acc0 = 0.f, acc1 = 0.f, acc2 = 0.f, acc3 = 0.f;
#pragma unroll
    for (int i = 0; i < 32; ++i) {
        const int d = w * 32 + i;
        const float m = s_mean[d];
        const float* Wr = W + (size_t)d * R_DIM;
        acc0 = fmaf(m, __ldg(&Wr[lane]),      acc0);
        acc1 = fmaf(m, __ldg(&Wr[32 + lane]), acc1);
        acc2 = fmaf(m, __ldg(&Wr[64 + lane]), acc2);
        acc3 = fmaf(m, __ldg(&Wr[96 + lane]), acc3);
    }
    s_red[w][lane]      = acc0;
    s_red[w][32 + lane] = acc1;
    s_red[w][64 + lane] = acc2;
    s_red[w][96 + lane] = acc3;
    __syncthreads();

    if (t < R_DIM) {
        float y = 0.f;
#pragma unroll
        for (int k = 0; k < 16; ++k)
            y += s_red[k][t];
        g_y[b * R_DIM + t] = y * pw[t];
    }
}

// ---------------------------------------------------------------------------
// K3: broadcast y via TMA bulk stores (SMEM -> GMEM), bypassing the STG path.
// Rounds 4+5 showed STG-based k3 pinned at ~3.7 TB/s regardless of ILP
// (DRAM=0%, L2=35%, issue=5%) -> SM store path is the wall, not L2.
// 256 blocks; block j: batch b = j>>5, 128KB segment seg = j&31.
// Each block replicates y[b] (512B) 32x into a 16KB SMEM image, then issues
// 8 x cp.async.bulk of 16KB. TMA engines stream 32MB at the LTS cap.
// ---------------------------------------------------------------------------
__global__ __launch_bounds__(256) void k3_broadcast_tma(float* __restrict__ out) {
    __shared__ __align__(128) float s_buf[4096];   // 16 KB
    const int j   = blockIdx.x;          // 0..255
    const int b   = j >> 5;              // 32 blocks per batch
    const int seg = j & 31;              // 128 KB segment within batch
    const int t   = threadIdx.x;         // 0..255

    // Fill SMEM: slot s (float4) holds y4[b*32 + (s&31)]; s = t + 256k keeps
    // (s&31) == (t&31), so one register value serves all 4 copies.
    const float4* y4 = reinterpret_cast<const float4*>(g_y);
    float4 v = __ldg(&y4[b * (R_DIM / 4) + (t & 31)]);
    float4* s4 = reinterpret_cast<float4*>(s_buf);
    s4[t]       = v;
    s4[t + 256] = v;
    s4[t + 512] = v;
    s4[t + 768] = v;
    __syncthreads();

    if (t == 0) {
        // Make generic-proxy SMEM writes visible to the async (TMA) proxy.
        asm volatile("fence.proxy.async.shared::cta;" ::: "memory");

        uint32_t saddr;
        asm("{ .reg .u64 a; cvta.to.shared.u64 a, %1; cvt.u32.u64 %0, a; }"
            : "=r"(saddr) : "l"(s_buf));

        float* gbase = out + (size_t)b * (N_DIM * R_DIM)
                           + (size_t)seg * 32768;          // 128 KB in floats
#pragma unroll
        for (int i = 0; i < 8; ++i) {
            asm volatile(
                "cp.async.bulk.global.shared::cta.bulk_group [%0], [%1], %2;"
                :: "l"(gbase + i * 4096), "r"(saddr), "r"(16384)
                : "memory");
        }
        asm volatile("cp.async.bulk.commit_group;" ::: "memory");
        asm volatile("cp.async.bulk.wait_group 0;" ::: "memory");
    }
}

// ---------------------------------------------------------------------------
extern "C" void kernel_launch(void* const* d_in, const int* in_sizes, int n_in,
                              void* d_out, int out_size) {
    const float* x  = (const float*)d_in[0];
    const float* W  = (const float*)d_in[1];
    const float* pw = (const float*)d_in[2];
    float* out      = (float*)d_out;

    (void)in_sizes; (void)n_in; (void)out_size;

    dim3 g1(CHUNKS, B_DIM);
    k1_colsum_partial<<<g1, 128>>>(x);

    dim3 g2a(G2, B_DIM);
    k2a_reduce<<<g2a, 128>>>();

    k2b_finish_and_project<<<B_DIM, 512>>>(W, pw);

    k3_broadcast_tma<<<256, 256>>>(out);
}